// round 16
// baseline (speedup 1.0000x reference)
#include <cuda_runtime.h>
#include <cuda_fp16.h>

#define N_NODES 16384
#define N_EDGES 262144
#define D_CH    256
#define BN_EPS  1e-5f

// ================= device scratch (no runtime allocation) ==================
__device__ __half g_x [N_NODES * D_CH];
__device__ __half g_e [N_NODES * D_CH];
__device__ __half g_e2[N_NODES * D_CH];
__device__ __half g_r [N_NODES * D_CH];
__device__ __half g_q [N_NODES * D_CH];

__device__ __half g_ew1h[N_NODES * D_CH];
__device__ __half g_ew2h[N_NODES * D_CH];

// stacked split weights, [N=256 rows][K'=512]: [hi(256) | lo(256)]
__device__ __half g_Bw1a[D_CH * 512];
__device__ __half g_Bf1a[D_CH * 512];
__device__ __half g_Bw1b[D_CH * 512];
__device__ __half g_Bf1b[D_CH * 512];
__device__ __half g_Bwx [D_CH * 512];
__device__ __half g_B2  [D_CH * 512];
__device__ __half g_Bf2 [D_CH * 512];

__device__ float g_wx1[D_CH * D_CH];
__device__ float g_wx2[D_CH * D_CH];
__device__ float g_G  [D_CH * D_CH];

__device__ float g_biasr[D_CH];
__device__ float g_bias3[D_CH];

__device__ float g_sum1[D_CH];
__device__ float g_sq1 [D_CH];
__device__ float g_sum2[D_CH];
__device__ float g_sq2 [D_CH];

__device__ int g_deg[N_NODES];       // zeroed at end of each run (scatter phase)
__device__ int g_off[N_NODES + 1];
__device__ int g_cur[N_NODES];
__device__ int g_csr[N_EDGES];

__device__ unsigned g_flags[256];    // grid barrier / publish flags (monotone)
__device__ unsigned g_pair [256];    // pair barrier flags (monotone)
__device__ unsigned g_scan;          // scan-done flag (monotone)
__device__ unsigned g_bflag[17];     // builder-done flags (monotone)

// ================= PTX helpers ==============================================
__device__ __forceinline__ unsigned smem_u32(const void* p) {
    unsigned a;
    asm("{ .reg .u64 t; cvta.to.shared.u64 t, %1; cvt.u32.u64 %0, t; }"
        : "=r"(a) : "l"(p));
    return a;
}
__device__ __forceinline__ void cp16(unsigned dst, const void* src) {
    asm volatile("cp.async.cg.shared.global [%0], [%1], 16;"
                 :: "r"(dst), "l"(src) : "memory");
}
__device__ __forceinline__ void cp_commit() {
    asm volatile("cp.async.commit_group;" ::: "memory");
}
template <int N>
__device__ __forceinline__ void cp_wait() {
    asm volatile("cp.async.wait_group %0;" :: "n"(N) : "memory");
}
__device__ __forceinline__ void ldsm_x4(unsigned* r, unsigned addr) {
    asm volatile("ldmatrix.sync.aligned.m8n8.x4.shared.b16 {%0,%1,%2,%3}, [%4];"
                 : "=r"(r[0]), "=r"(r[1]), "=r"(r[2]), "=r"(r[3]) : "r"(addr));
}
__device__ __forceinline__ void mma_fp16(float* c, const unsigned* a, const unsigned* b) {
    asm volatile(
        "mma.sync.aligned.m16n8k16.row.col.f32.f16.f16.f32 "
        "{%0,%1,%2,%3}, {%4,%5,%6,%7}, {%8,%9}, {%0,%1,%2,%3};"
        : "+f"(c[0]), "+f"(c[1]), "+f"(c[2]), "+f"(c[3])
        : "r"(a[0]), "r"(a[1]), "r"(a[2]), "r"(a[3]), "r"(b[0]), "r"(b[1]));
}
__device__ __forceinline__ void split1h(float v, __half& h, __half& l) {
    h = __float2half_rn(v);
    l = __float2half_rn(v - __half2float(h));
}
__device__ __forceinline__ uint2 pack4h(float4 v) {
    __half2 a = __floats2half2_rn(v.x, v.y);
    __half2 b = __floats2half2_rn(v.z, v.w);
    uint2 r;
    r.x = *(unsigned*)&a;
    r.y = *(unsigned*)&b;
    return r;
}

// ================= sync primitives ==========================================
__device__ __forceinline__ void grid_bar(unsigned gen) {
    __syncthreads();
    __threadfence();
    if (threadIdx.x == 0) atomicExch(&g_flags[blockIdx.x], gen);
    for (;;) {
        unsigned v = __ldcg(&g_flags[threadIdx.x]);
        if (__syncthreads_and((int)(v - gen) >= 0)) break;
        __nanosleep(128);
    }
    __threadfence();
}
__device__ __forceinline__ void pair_bar(unsigned gen) {
    __syncthreads();
    __threadfence();
    if (threadIdx.x == 0) {
        atomicExch(&g_pair[blockIdx.x], gen);
        while ((int)(__ldcg(&g_pair[blockIdx.x ^ 1]) - gen) < 0) __nanosleep(64);
    }
    __syncthreads();
}
// publish without waiting
__device__ __forceinline__ void publish(unsigned gen) {
    __syncthreads();
    __threadfence();
    if (threadIdx.x == 0) atomicExch(&g_flags[blockIdx.x], gen);
}
// wait until all 256 CTAs have published gen
__device__ __forceinline__ void wait_all(unsigned gen) {
    for (;;) {
        unsigned v = __ldcg(&g_flags[threadIdx.x]);
        if (__syncthreads_and((int)(v - gen) >= 0)) break;
        __nanosleep(128);
    }
    __threadfence();
}
// wait until all 17 builders have published gen
__device__ __forceinline__ void wait17(unsigned gen) {
    for (;;) {
        unsigned v = (threadIdx.x < 17) ? __ldcg(&g_bflag[threadIdx.x]) : gen;
        if (__syncthreads_and((int)(v - gen) >= 0)) break;
        __nanosleep(64);
    }
    __threadfence();
}

// ================= phase pieces ==============================================
__device__ void conv_unit(unsigned u, const float* x, const float* ew1,
                          const float* ew2) {
    if (u < 4096) {
        int i = u * 256 + threadIdx.x;
        ((uint2*)g_x)[i] = pack4h(((const float4*)x)[i]);
    } else if (u < 8192) {
        int i = (u - 4096) * 256 + threadIdx.x;
        ((uint2*)g_ew1h)[i] = pack4h(((const float4*)ew1)[i]);
    } else if (u < 12288) {
        int i = (u - 8192) * 256 + threadIdx.x;
        ((uint2*)g_ew2h)[i] = pack4h(((const float4*)ew2)[i]);
    } else {
        int j = threadIdx.x;
        g_sum1[j] = 0.f; g_sq1[j] = 0.f;
        g_sum2[j] = 0.f; g_sq2[j] = 0.f;
    }
}

template <bool ADD_A>
__device__ __noinline__ void wx_tile(char* sm, const float* A, const float* B,
                                     float* Cf, int bm, int bn) {
    float* As = (float*)sm;
    float* Bs = As + 16 * 64;
    int tx = threadIdx.x & 15, ty = threadIdx.x >> 4;
    int r = threadIdx.x >> 2, c4 = (threadIdx.x & 3) * 4;
    int rb = threadIdx.x >> 4, cb = (threadIdx.x & 15) * 4;
    float acc[4][4] = {};
    float4 av = *(const float4*)(A + (bm + r) * 256 + c4);
    float4 bv = *(const float4*)(B + rb * 256 + bn + cb);
    for (int kt = 0; kt < 256; kt += 16) {
        As[(c4 + 0) * 64 + r] = av.x; As[(c4 + 1) * 64 + r] = av.y;
        As[(c4 + 2) * 64 + r] = av.z; As[(c4 + 3) * 64 + r] = av.w;
        *(float4*)&Bs[rb * 68 + cb] = bv;
        __syncthreads();
        if (kt < 240) {
            av = *(const float4*)(A + (bm + r) * 256 + kt + 16 + c4);
            bv = *(const float4*)(B + (kt + 16 + rb) * 256 + bn + cb);
        }
#pragma unroll
        for (int k = 0; k < 16; k++) {
            float a[4], b[4];
#pragma unroll
            for (int i = 0; i < 4; i++) a[i] = As[k * 64 + ty * 4 + i];
#pragma unroll
            for (int j = 0; j < 4; j++) b[j] = Bs[k * 68 + tx * 4 + j];
#pragma unroll
            for (int i = 0; i < 4; i++)
#pragma unroll
                for (int j = 0; j < 4; j++) acc[i][j] = fmaf(a[i], b[j], acc[i][j]);
        }
        __syncthreads();
    }
#pragma unroll
    for (int i = 0; i < 4; i++) {
        int k = bm + ty * 4 + i;
#pragma unroll
        for (int j = 0; j < 4; j++)
            Cf[k * 256 + bn + tx * 4 + j] = acc[i][j] + (ADD_A ? A[k * 256 + bn + tx * 4 + j] : 0.f);
    }
    __syncthreads();
}

__device__ __noinline__ void split_tile(char* sm, const float* W, __half* Bo,
                                        bool addI, int t) {
    float* T = (float*)sm;
    int kt = (t & 3) * 64, nt = (t >> 2) * 64;
    int r4 = threadIdx.x >> 6, c = threadIdx.x & 63;
#pragma unroll
    for (int i = 0; i < 16; i++) {
        int row = i * 4 + r4;
        float w = W[(kt + row) * 256 + nt + c];
        if (addI && (kt + row) == (nt + c)) w += 1.f;
        T[row * 65 + c] = w;
    }
    __syncthreads();
#pragma unroll
    for (int i = 0; i < 16; i++) {
        int nl = i * 4 + r4;
        __half h, l;
        split1h(T[c * 65 + nl], h, l);
        Bo[(nt + nl) * 512 + kt + c]       = h;
        Bo[(nt + nl) * 512 + 256 + kt + c] = l;
    }
    __syncthreads();
}

__device__ __noinline__ void split_tile_sc(char* sm, const float* W, __half* Bo,
                                           const float* sums, const float* sqs,
                                           const float* gamma, int t) {
    const float inv_n = 1.f / (float)N_NODES;
    float* T = (float*)sm;
    float* sc = T + 64 * 65;
    int kt = (t & 3) * 64, nt = (t >> 2) * 64;
    if (threadIdx.x < 64) {
        int k = kt + threadIdx.x;
        float mu = __ldcg(sums + k) * inv_n;
        float var = __ldcg(sqs + k) * inv_n - mu * mu;
        sc[threadIdx.x] = rsqrtf(var + BN_EPS) * gamma[k];
    }
    __syncthreads();
    int r4 = threadIdx.x >> 6, c = threadIdx.x & 63;
#pragma unroll
    for (int i = 0; i < 16; i++) {
        int row = i * 4 + r4;
        T[row * 65 + c] = sc[row] * W[(kt + row) * 256 + nt + c];
    }
    __syncthreads();
#pragma unroll
    for (int i = 0; i < 16; i++) {
        int nl = i * 4 + r4;
        __half h, l;
        split1h(T[c * 65 + nl], h, l);
        Bo[(nt + nl) * 512 + kt + c]       = h;
        Bo[(nt + nl) * 512 + 256 + kt + c] = l;
    }
    __syncthreads();
}

__device__ __noinline__ void scan256(char* sm) {
    int* sd = (int*)sm;
    int* ps = sd + 16384;
    int t = threadIdx.x;
    for (int i = t; i < N_NODES; i += 256) sd[i] = g_deg[i];
    __syncthreads();
    int base = t * 64;
    int sum = 0;
#pragma unroll 8
    for (int i = 0; i < 64; i++) sum += sd[base + i];
    ps[t] = sum;
    __syncthreads();
    for (int d = 1; d < 256; d <<= 1) {
        int v = (t >= d) ? ps[t - d] : 0;
        __syncthreads();
        if (t >= d) ps[t] += v;
        __syncthreads();
    }
    int run = (t == 0) ? 0 : ps[t - 1];
#pragma unroll 8
    for (int i = 0; i < 64; i++) {
        int v = sd[base + i];
        g_off[base + i] = run;
        g_cur[base + i] = run;
        run += v;
    }
    if (t == 255) g_off[N_NODES] = run;
    __syncthreads();
}

__device__ void spmm_unit2(int u, const float* eb1, const float* eb2) {
    int node = u * 4 + (threadIdx.x >> 6);
    int c = threadIdx.x & 63;
    const uint2* w1 = (const uint2*)g_ew1h;
    const uint2* w2 = (const uint2*)g_ew2h;
    float4 a1 = ((const float4*)eb1)[c];
    float4 a2 = ((const float4*)eb2)[c];
    int s = g_off[node];
    int e = g_off[node + 1];
    for (int k = s; k < e; k++) {
        int j = g_csr[k] * 64 + c;
        uint2 v1 = w1[j];
        uint2 v2 = w2[j];
        float2 p0 = __half22float2(*(const __half2*)&v1.x);
        float2 p1 = __half22float2(*(const __half2*)&v1.y);
        a1.x += p0.x; a1.y += p0.y; a1.z += p1.x; a1.w += p1.y;
        float2 q0 = __half22float2(*(const __half2*)&v2.x);
        float2 q1 = __half22float2(*(const __half2*)&v2.y);
        a2.x += q0.x; a2.y += q0.y; a2.z += q1.x; a2.w += q1.y;
    }
    ((uint2*)g_e)[node * 64 + c]  = pack4h(a1);
    ((uint2*)g_e2)[node * 64 + c] = pack4h(a2);
}

// ================= HMMA fp16 2-term GEMM phase ==============================
#define STAGES   3
#define BUF_SZ   32768
#define STATS_OFF (STAGES * BUF_SZ)
#define SMEM_MMA (STATS_OFF + 1024)

// WGEN != 0 (MODE 1): before issuing chunk 8 (first B2-dependent load),
// wait for all 17 builder flags to reach wgen.
template <int MODE, bool F32S, bool HST, bool XCOPY>
__device__ __noinline__ void gemm_phase(char* smem, int cta,
        const __half* A, const __half* A2,
        const __half* Bb, const __half* B2b,
        const float* bias,
        float* outf, int ldout, __half* oh,
        float* sumP, float* sqP, const float* xsrc,
        unsigned wgen) {
    const unsigned sbase = smem_u32(smem);
    const int tid = threadIdx.x;
    const int lane = tid & 31;
    const int w = tid >> 5;
    const int wm = w & 3;
    const int wn = w >> 2;
    const int bm = (cta >> 1) * 128;
    const int bn = (cta & 1) * 128;

    const int NC = (MODE == 1) ? 16 : 8;

    auto issue = [&](int c) {
        const bool second = (MODE == 1) && (c >= 8);
        const int local = second ? c - 8 : c;
        const __half* Ap = second ? A2 : A;
        const __half* Bp = second ? B2b : Bb;
        const int ka = (local & 3) << 6;
        const int kb = local << 6;
        const unsigned sa = sbase + (c % STAGES) * BUF_SZ;
        const unsigned sb = sa + 16384;
#pragma unroll
        for (int i = 0; i < 4; i++) {
            int u = tid + (i << 8);
            int row = u >> 3, seg = u & 7;
            cp16(sa + row * 128 + ((seg ^ (row & 7)) << 4),
                 Ap + ((bm + row) << 8) + ka + (seg << 3));
        }
#pragma unroll
        for (int i = 0; i < 4; i++) {
            int u = tid + (i << 8);
            int row = u >> 3, seg = u & 7;
            cp16(sb + row * 128 + ((seg ^ (row & 7)) << 4),
                 Bp + (bn + row) * 512 + kb + (seg << 3));
        }
        cp_commit();
    };

    const int a_row = wm * 32 + (lane & 15);
    const int a_kh = lane >> 4;
    const int b_nrel = ((lane >> 4) << 3) + (lane & 7);
    const int b_n = wn * 64 + b_nrel;
    const int b_kh = (lane >> 3) & 1;

    float acc[2][8][4];
#pragma unroll
    for (int mt = 0; mt < 2; mt++)
#pragma unroll
        for (int nt = 0; nt < 8; nt++)
#pragma unroll
            for (int q = 0; q < 4; q++) acc[mt][nt][q] = 0.f;

    issue(0); issue(1); issue(2);

    for (int c = 0; c < NC; c++) {
        if (c >= NC - 2) cp_wait<0>(); else cp_wait<STAGES - 1>();
        __syncthreads();
        const unsigned sa = sbase + (c % STAGES) * BUF_SZ;
        const unsigned sb = sa + 16384;
#pragma unroll
        for (int ks = 0; ks < 4; ks++) {
            const int seg0 = ks * 2;
            unsigned af[2][4];
#pragma unroll
            for (int mt = 0; mt < 2; mt++) {
                int r = a_row + mt * 16;
                ldsm_x4(af[mt], sa + r * 128 + (((seg0 + a_kh) ^ (r & 7)) << 4));
            }
            unsigned bf[8][2];
#pragma unroll
            for (int np = 0; np < 4; np++) {
                int n = b_n + np * 16;
                unsigned t4[4];
                ldsm_x4(t4, sb + n * 128 + (((seg0 + b_kh) ^ (n & 7)) << 4));
                bf[np * 2][0] = t4[0]; bf[np * 2][1] = t4[1];
                bf[np * 2 + 1][0] = t4[2]; bf[np * 2 + 1][1] = t4[3];
            }
#pragma unroll
            for (int mt = 0; mt < 2; mt++)
#pragma unroll
                for (int nt = 0; nt < 8; nt++)
                    mma_fp16(acc[mt][nt], af[mt], bf[nt]);
        }
        __syncthreads();
        if (MODE == 1 && wgen && c + STAGES == 8) wait17(wgen);
        if (c + STAGES < NC) issue(c + STAGES);
    }
    __syncthreads();

    const int er = lane >> 2;
    const int ec = (lane & 3) << 1;
#pragma unroll
    for (int mt = 0; mt < 2; mt++) {
#pragma unroll
        for (int nt = 0; nt < 8; nt++) {
            int r0 = wm * 32 + mt * 16 + er;
            int cc = wn * 64 + nt * 8 + ec;
            float b0 = __ldcg(bias + bn + cc), b1 = __ldcg(bias + bn + cc + 1);
            float v0 = acc[mt][nt][0] + b0, v1 = acc[mt][nt][1] + b1;
            float v2 = acc[mt][nt][2] + b0, v3 = acc[mt][nt][3] + b1;
            if (MODE == 1 || MODE == 2) {
                v0 = fmaxf(v0, 0.f); v1 = fmaxf(v1, 0.f);
                v2 = fmaxf(v2, 0.f); v3 = fmaxf(v3, 0.f);
            }
            int r1 = r0 + 8;
            *(float2*)(smem + r0 * 512 + ((((cc >> 2) ^ ((r0 & 7) << 2))) << 4) + ((cc & 3) << 2)) = make_float2(v0, v1);
            *(float2*)(smem + r1 * 512 + ((((cc >> 2) ^ ((r1 & 7) << 2))) << 4) + ((cc & 3) << 2)) = make_float2(v2, v3);
        }
    }
    __syncthreads();

#pragma unroll 4
    for (int i = 0; i < 16; i++) {
        int u = tid + (i << 8);
        int r = u >> 5, seg = u & 31;
        float4 v = *(const float4*)(smem + r * 512 + ((seg ^ ((r & 7) << 2)) << 4));
        int grow = bm + r;
        int gcol = bn + (seg << 2);
        if (F32S) {
            *(float4*)(outf + grow * ldout + gcol) = v;
            if (XCOPY) {
                float4 xv = ((const float4*)xsrc)[(grow << 6) + (gcol >> 2)];
                *(float4*)(outf + grow * ldout + 256 + gcol) = xv;
            }
        }
        if (HST)  ((uint2*)oh)[(grow << 6) + (gcol >> 2)] = pack4h(v);
    }

    if (MODE == 2) {
        int c = tid & 127, r0 = (tid >> 7) << 6;
        float s = 0.f, q = 0.f;
#pragma unroll 4
        for (int rr = 0; rr < 64; rr++) {
            int r = r0 + rr;
            float v = *(const float*)(smem + r * 512 +
                                      ((((c >> 2) ^ ((r & 7) << 2))) << 4) + ((c & 3) << 2));
            s += v;
            q += v * v;
        }
        float* st = (float*)(smem + STATS_OFF);
        __syncthreads();
        if (tid >= 128) { st[c] = s; st[128 + c] = q; }
        __syncthreads();
        if (tid < 128) {
            atomicAdd(&sumP[bn + c], s + st[c]);
            atomicAdd(&sqP [bn + c], q + st[128 + c]);
        }
    }
    __syncthreads();
}

// ================= the mega kernel ==========================================
struct Params {
    const float* x;
    const int* ei;
    const float* P1[14];
    const float* P2[14];
    float* out;
};

__global__ __launch_bounds__(256, 2) void mega_k(Params P) {
    extern __shared__ char smem[];
    const int cta = blockIdx.x;
    unsigned gen = __ldcg(&g_flags[cta]);

    // ---- P0: conversions (all CTAs) + wx tiles + hist + biasr1 ----
    if (cta < 16) {
        wx_tile<true>(smem, P.P2[2], P.P2[6], g_wx2, (cta >> 2) * 64, (cta & 3) * 64);
    } else if (cta < 32) {
        wx_tile<true>(smem, P.P1[2], P.P1[6], g_wx1, ((cta - 16) >> 2) * 64, ((cta - 16) & 3) * 64);
    } else if (cta == 32) {
        int n = threadIdx.x;
        float s = P.P1[5][n] + P.P1[7][n] + P.P1[3][n];
        for (int k = 0; k < 256; k++) s += P.P1[3][k] * P.P1[6][k * 256 + n];
        g_biasr[n] = s;
    } else if (cta < 97) {
        for (int u = cta - 33; u < 1024; u += 64) {
            int e = u * 256 + threadIdx.x;
            atomicAdd(&g_deg[P.ei[N_EDGES + e]], 1);
        }
    }
    for (unsigned u = cta; u < 12289u; u += 256)
        conv_unit(u, P.x, P.P1[0], P.P2[0]);
    grid_bar(++gen);

    // ---- P1: scan (CTA 0) || G tiles || splitw tiles; scan-flag sync ----
    if (cta == 0) {
        scan256(smem);
    } else if (cta < 17) {
        wx_tile<false>(smem, P.P1[12], g_wx2, g_G, ((cta - 1) >> 2) * 64, ((cta - 1) & 3) * 64);
    } else if (cta < 97) {
        int b = cta - 17;
        int mat = b >> 4, t = b & 15;
        const float* W;
        __half* B;
        bool addI = false;
        switch (mat) {
            case 0: W = P.P1[4]; B = g_Bw1a; addI = true; break;
            case 1: W = P.P1[8]; B = g_Bf1a; break;
            case 2: W = P.P2[4]; B = g_Bw1b; addI = true; break;
            case 3: W = P.P2[8]; B = g_Bf1b; break;
            default: W = g_wx1;  B = g_Bwx; break;
        }
        split_tile(smem, W, B, addI, t);
    }
    ++gen;
    if (cta == 0) {
        __syncthreads();
        __threadfence();
        if (threadIdx.x == 0) atomicExch(&g_scan, gen);
    }
    for (;;) {
        unsigned v = __ldcg(&g_scan);
        if (__syncthreads_and((int)(v - gen) >= 0)) break;
        __nanosleep(128);
    }
    __threadfence();

    // ---- P2: scatter + zero g_deg for next run ----
    for (int u = cta; u < 1024; u += 256) {
        int e = u * 256 + threadIdx.x;
        int d = P.ei[N_EDGES + e];
        int p = atomicAdd(&g_cur[d], 1);
        g_csr[p] = P.ei[e];
    }
    if (cta < 64) g_deg[cta * 256 + threadIdx.x] = 0;
    grid_bar(++gen);

    // ---- P3: merged spmm, pair-local rows ----
    {
        int u0 = (cta >> 1) * 32 + (cta & 1) * 16;
        for (int u = u0; u < u0 + 16; u++)
            spmm_unit2(u, P.P1[1], P.P2[1]);
    }
    pair_bar(++gen);

    // ---- P4: r1 = relu(emb1@(I+c1w1) + x@wx1 + biasr1) ----
    gemm_phase<1, false, true, false>(smem, cta, g_e, g_x, g_Bw1a, g_Bwx,
                                      g_biasr, nullptr, 0, g_r,
                                      nullptr, nullptr, nullptr, 0);
    pair_bar(++gen);

    // ---- P5: q1 = relu(r1@f1w1 + f1b1), stats1; publish (no global wait) ----
    gemm_phase<2, false, true, false>(smem, cta, g_r, nullptr, g_Bf1a, nullptr,
                                      P.P1[9], nullptr, 0, g_q,
                                      g_sum1, g_sq1, nullptr, 0);
    ++gen;
    publish(gen);

    // Builders (CTAs 0-16): wait for all stats, build B2 + layer2 bias, flag.
    if (cta < 17) {
        wait_all(gen);
        if (cta < 16) {
            split_tile_sc(smem, g_G, g_B2, g_sum1, g_sq1, P.P1[10], cta);
        } else {
            const float inv_n = 1.f / (float)N_NODES;
            int n = threadIdx.x;
            float s = P.P2[5][n] + P.P2[7][n] + P.P2[3][n];
            for (int k = 0; k < 256; k++) {
                float mu = __ldcg(g_sum1 + k) * inv_n;
                float var = __ldcg(g_sq1 + k) * inv_n - mu * mu;
                float rs = rsqrtf(var + BN_EPS);
                float t1 = P.P1[11][k] - mu * rs * P.P1[10][k];
                s += P.P2[3][k] * P.P2[6][k * 256 + n] + t1 * g_G[(k << 8) + n]
                   + P.P1[13][k] * g_wx2[(k << 8) + n];
            }
            g_biasr[n] = s;
        }
        __syncthreads();
        __threadfence();
        if (threadIdx.x == 0) atomicExch(&g_bflag[cta], gen);
    }

    // ---- P6: r2 = relu(emb2@(I+c1w2) + q1@B2 + biasr2) ----
    // First 8 chunks (e2 x Bw1b) run immediately; waits on builders before
    // the first B2-dependent load (chunk 8).
    gemm_phase<1, false, true, false>(smem, cta, g_e2, g_q, g_Bw1b, g_B2,
                                      g_biasr, nullptr, 0, g_r,
                                      nullptr, nullptr, nullptr, gen);
    pair_bar(++gen);

    // ---- P7: q2 = relu(r2@f1w2 + f1b2), stats2; publish ----
    gemm_phase<2, false, true, false>(smem, cta, g_r, nullptr, g_Bf1b, nullptr,
                                      P.P2[9], nullptr, 0, g_q,
                                      g_sum2, g_sq2, nullptr, 0);
    ++gen;
    publish(gen);

    // Builders: wait all stats2, build Bf2 + bias3, flag.
    if (cta < 17) {
        wait_all(gen);
        if (cta < 16) {
            split_tile_sc(smem, P.P2[12], g_Bf2, g_sum2, g_sq2, P.P2[10], cta);
        } else {
            const float inv_n = 1.f / (float)N_NODES;
            int n = threadIdx.x;
            float s = P.P2[13][n];
            for (int k = 0; k < 256; k++) {
                float mu = __ldcg(g_sum2 + k) * inv_n;
                float var = __ldcg(g_sq2 + k) * inv_n - mu * mu;
                float rs = rsqrtf(var + BN_EPS);
                s += (P.P2[11][k] - mu * rs * P.P2[10][k]) * P.P2[12][(k << 8) + n];
            }
            g_bias3[n] = s;
        }
        __syncthreads();
        __threadfence();
        if (threadIdx.x == 0) atomicExch(&g_bflag[cta], gen);
    }
    // all CTAs wait for Bf2/bias3 before the final GEMM
    wait17(gen);

    // ---- P8: out[:,0:256] = (q2*s2+t2)@f2w2 + f2b2 ; out[:,256:512] = x ----
    gemm_phase<3, true, false, true>(smem, cta, g_q, nullptr, g_Bf2, nullptr,
                                     g_bias3, P.out, 512, nullptr,
                                     nullptr, nullptr, P.x, 0);
}

// ================= host orchestration ========================================
extern "C" void kernel_launch(void* const* d_in, const int* in_sizes, int n_in,
                              void* d_out, int out_size) {
    (void)in_sizes; (void)n_in; (void)out_size;

    Params P;
    P.x  = (const float*)d_in[0];
    P.ei = (const int*)d_in[2];
    for (int i = 0; i < 14; i++) {
        P.P1[i] = (const float*)d_in[4 + i];
        P.P2[i] = (const float*)d_in[18 + i];
    }
    P.out = (float*)d_out;

    cudaFuncSetAttribute(mega_k, cudaFuncAttributeMaxDynamicSharedMemorySize,
                         SMEM_MMA);

    mega_k<<<256, 256, SMEM_MMA>>>(P);
}

// round 17
// speedup vs baseline: 1.0816x; 1.0816x over previous
#include <cuda_runtime.h>
#include <cuda_fp16.h>

#define N_NODES 16384
#define N_EDGES 262144
#define D_CH    256
#define BN_EPS  1e-5f

// ================= device scratch (no runtime allocation) ==================
__device__ __half g_x [N_NODES * D_CH];
__device__ __half g_e [N_NODES * D_CH];
__device__ __half g_e2[N_NODES * D_CH];
__device__ __half g_r [N_NODES * D_CH];
__device__ __half g_q [N_NODES * D_CH];

__device__ __half g_ew1h[N_NODES * D_CH];
__device__ __half g_ew2h[N_NODES * D_CH];

// stacked split weights, [N=256 rows][K'=512]: [hi(256) | lo(256)]
__device__ __half g_Bw1a[D_CH * 512];
__device__ __half g_Bf1a[D_CH * 512];
__device__ __half g_Bw1b[D_CH * 512];
__device__ __half g_Bf1b[D_CH * 512];
__device__ __half g_Bwx [D_CH * 512];
__device__ __half g_B2  [D_CH * 512];
__device__ __half g_Bf2 [D_CH * 512];

__device__ float g_wx1[D_CH * D_CH];
__device__ float g_wx2[D_CH * D_CH];
__device__ float g_G  [D_CH * D_CH];

__device__ float g_biasr[D_CH];
__device__ float g_bias3[D_CH];

__device__ float g_sum1[D_CH];
__device__ float g_sq1 [D_CH];
__device__ float g_sum2[D_CH];
__device__ float g_sq2 [D_CH];

__device__ int g_deg[N_NODES];       // zeroed in the scatter phase each run
__device__ int g_off[N_NODES + 1];
__device__ int g_cur[N_NODES];
__device__ int g_csr[N_EDGES];

__device__ unsigned g_flags[256];    // grid barrier / publish flags (monotone)
__device__ unsigned g_pair [256];    // pair barrier flags (monotone)
__device__ unsigned g_scan;          // scan-done flag (monotone)
__device__ unsigned g_bflag[17];     // builder-done flags (monotone)

// ================= PTX helpers ==============================================
__device__ __forceinline__ unsigned smem_u32(const void* p) {
    unsigned a;
    asm("{ .reg .u64 t; cvta.to.shared.u64 t, %1; cvt.u32.u64 %0, t; }"
        : "=r"(a) : "l"(p));
    return a;
}
__device__ __forceinline__ void cp16(unsigned dst, const void* src) {
    asm volatile("cp.async.cg.shared.global [%0], [%1], 16;"
                 :: "r"(dst), "l"(src) : "memory");
}
__device__ __forceinline__ void cp_commit() {
    asm volatile("cp.async.commit_group;" ::: "memory");
}
template <int N>
__device__ __forceinline__ void cp_wait() {
    asm volatile("cp.async.wait_group %0;" :: "n"(N) : "memory");
}
__device__ __forceinline__ void ldsm_x4(unsigned* r, unsigned addr) {
    asm volatile("ldmatrix.sync.aligned.m8n8.x4.shared.b16 {%0,%1,%2,%3}, [%4];"
                 : "=r"(r[0]), "=r"(r[1]), "=r"(r[2]), "=r"(r[3]) : "r"(addr));
}
__device__ __forceinline__ void mma_fp16(float* c, const unsigned* a, const unsigned* b) {
    asm volatile(
        "mma.sync.aligned.m16n8k16.row.col.f32.f16.f16.f32 "
        "{%0,%1,%2,%3}, {%4,%5,%6,%7}, {%8,%9}, {%0,%1,%2,%3};"
        : "+f"(c[0]), "+f"(c[1]), "+f"(c[2]), "+f"(c[3])
        : "r"(a[0]), "r"(a[1]), "r"(a[2]), "r"(a[3]), "r"(b[0]), "r"(b[1]));
}
__device__ __forceinline__ void split1h(float v, __half& h, __half& l) {
    h = __float2half_rn(v);
    l = __float2half_rn(v - __half2float(h));
}
__device__ __forceinline__ uint2 pack4h(float4 v) {
    __half2 a = __floats2half2_rn(v.x, v.y);
    __half2 b = __floats2half2_rn(v.z, v.w);
    uint2 r;
    r.x = *(unsigned*)&a;
    r.y = *(unsigned*)&b;
    return r;
}

// ================= sync primitives ==========================================
__device__ __forceinline__ void grid_bar(unsigned gen) {
    __syncthreads();
    __threadfence();
    if (threadIdx.x == 0) atomicExch(&g_flags[blockIdx.x], gen);
    for (;;) {
        unsigned v = __ldcg(&g_flags[threadIdx.x]);
        if (__syncthreads_and((int)(v - gen) >= 0)) break;
        __nanosleep(128);
    }
    __threadfence();
}
__device__ __forceinline__ void pair_bar(unsigned gen) {
    __syncthreads();
    __threadfence();
    if (threadIdx.x == 0) {
        atomicExch(&g_pair[blockIdx.x], gen);
        while ((int)(__ldcg(&g_pair[blockIdx.x ^ 1]) - gen) < 0) __nanosleep(64);
    }
    __syncthreads();
}
__device__ __forceinline__ void publish(unsigned gen) {
    __syncthreads();
    __threadfence();
    if (threadIdx.x == 0) atomicExch(&g_flags[blockIdx.x], gen);
}
__device__ __forceinline__ void wait_all(unsigned gen) {
    for (;;) {
        unsigned v = __ldcg(&g_flags[threadIdx.x]);
        if (__syncthreads_and((int)(v - gen) >= 0)) break;
        __nanosleep(128);
    }
    __threadfence();
}
__device__ __forceinline__ void wait17(unsigned gen) {
    for (;;) {
        unsigned v = (threadIdx.x < 17) ? __ldcg(&g_bflag[threadIdx.x]) : gen;
        if (__syncthreads_and((int)(v - gen) >= 0)) break;
        __nanosleep(64);
    }
    __threadfence();
}

// ================= phase pieces ==============================================
__device__ void conv_unit(unsigned u, const float* x, const float* ew1,
                          const float* ew2) {
    if (u < 4096) {
        int i = u * 256 + threadIdx.x;
        ((uint2*)g_x)[i] = pack4h(((const float4*)x)[i]);
    } else if (u < 8192) {
        int i = (u - 4096) * 256 + threadIdx.x;
        ((uint2*)g_ew1h)[i] = pack4h(((const float4*)ew1)[i]);
    } else if (u < 12288) {
        int i = (u - 8192) * 256 + threadIdx.x;
        ((uint2*)g_ew2h)[i] = pack4h(((const float4*)ew2)[i]);
    } else {
        int j = threadIdx.x;
        g_sum1[j] = 0.f; g_sq1[j] = 0.f;
        g_sum2[j] = 0.f; g_sq2[j] = 0.f;
    }
}

template <bool ADD_A>
__device__ __noinline__ void wx_tile(char* sm, const float* A, const float* B,
                                     float* Cf, int bm, int bn) {
    float* As = (float*)sm;
    float* Bs = As + 16 * 64;
    int tx = threadIdx.x & 15, ty = threadIdx.x >> 4;
    int r = threadIdx.x >> 2, c4 = (threadIdx.x & 3) * 4;
    int rb = threadIdx.x >> 4, cb = (threadIdx.x & 15) * 4;
    float acc[4][4] = {};
    float4 av = *(const float4*)(A + (bm + r) * 256 + c4);
    float4 bv = *(const float4*)(B + rb * 256 + bn + cb);
    for (int kt = 0; kt < 256; kt += 16) {
        As[(c4 + 0) * 64 + r] = av.x; As[(c4 + 1) * 64 + r] = av.y;
        As[(c4 + 2) * 64 + r] = av.z; As[(c4 + 3) * 64 + r] = av.w;
        *(float4*)&Bs[rb * 68 + cb] = bv;
        __syncthreads();
        if (kt < 240) {
            av = *(const float4*)(A + (bm + r) * 256 + kt + 16 + c4);
            bv = *(const float4*)(B + (kt + 16 + rb) * 256 + bn + cb);
        }
#pragma unroll
        for (int k = 0; k < 16; k++) {
            float a[4], b[4];
#pragma unroll
            for (int i = 0; i < 4; i++) a[i] = As[k * 64 + ty * 4 + i];
#pragma unroll
            for (int j = 0; j < 4; j++) b[j] = Bs[k * 68 + tx * 4 + j];
#pragma unroll
            for (int i = 0; i < 4; i++)
#pragma unroll
                for (int j = 0; j < 4; j++) acc[i][j] = fmaf(a[i], b[j], acc[i][j]);
        }
        __syncthreads();
    }
#pragma unroll
    for (int i = 0; i < 4; i++) {
        int k = bm + ty * 4 + i;
#pragma unroll
        for (int j = 0; j < 4; j++)
            Cf[k * 256 + bn + tx * 4 + j] = acc[i][j] + (ADD_A ? A[k * 256 + bn + tx * 4 + j] : 0.f);
    }
    __syncthreads();
}

__device__ __noinline__ void split_tile(char* sm, const float* W, __half* Bo,
                                        bool addI, int t) {
    float* T = (float*)sm;
    int kt = (t & 3) * 64, nt = (t >> 2) * 64;
    int r4 = threadIdx.x >> 6, c = threadIdx.x & 63;
#pragma unroll
    for (int i = 0; i < 16; i++) {
        int row = i * 4 + r4;
        float w = W[(kt + row) * 256 + nt + c];
        if (addI && (kt + row) == (nt + c)) w += 1.f;
        T[row * 65 + c] = w;
    }
    __syncthreads();
#pragma unroll
    for (int i = 0; i < 16; i++) {
        int nl = i * 4 + r4;
        __half h, l;
        split1h(T[c * 65 + nl], h, l);
        Bo[(nt + nl) * 512 + kt + c]       = h;
        Bo[(nt + nl) * 512 + 256 + kt + c] = l;
    }
    __syncthreads();
}

__device__ __noinline__ void split_tile_sc(char* sm, const float* W, __half* Bo,
                                           const float* sums, const float* sqs,
                                           const float* gamma, int t) {
    const float inv_n = 1.f / (float)N_NODES;
    float* T = (float*)sm;
    float* sc = T + 64 * 65;
    int kt = (t & 3) * 64, nt = (t >> 2) * 64;
    if (threadIdx.x < 64) {
        int k = kt + threadIdx.x;
        float mu = __ldcg(sums + k) * inv_n;
        float var = __ldcg(sqs + k) * inv_n - mu * mu;
        sc[threadIdx.x] = rsqrtf(var + BN_EPS) * gamma[k];
    }
    __syncthreads();
    int r4 = threadIdx.x >> 6, c = threadIdx.x & 63;
#pragma unroll
    for (int i = 0; i < 16; i++) {
        int row = i * 4 + r4;
        T[row * 65 + c] = sc[row] * W[(kt + row) * 256 + nt + c];
    }
    __syncthreads();
#pragma unroll
    for (int i = 0; i < 16; i++) {
        int nl = i * 4 + r4;
        __half h, l;
        split1h(T[c * 65 + nl], h, l);
        Bo[(nt + nl) * 512 + kt + c]       = h;
        Bo[(nt + nl) * 512 + 256 + kt + c] = l;
    }
    __syncthreads();
}

__device__ __noinline__ void scan256(char* sm) {
    int* sd = (int*)sm;
    int* ps = sd + 16384;
    int t = threadIdx.x;
    for (int i = t; i < N_NODES; i += 256) sd[i] = g_deg[i];
    __syncthreads();
    int base = t * 64;
    int sum = 0;
#pragma unroll 8
    for (int i = 0; i < 64; i++) sum += sd[base + i];
    ps[t] = sum;
    __syncthreads();
    for (int d = 1; d < 256; d <<= 1) {
        int v = (t >= d) ? ps[t - d] : 0;
        __syncthreads();
        if (t >= d) ps[t] += v;
        __syncthreads();
    }
    int run = (t == 0) ? 0 : ps[t - 1];
#pragma unroll 8
    for (int i = 0; i < 64; i++) {
        int v = sd[base + i];
        g_off[base + i] = run;
        g_cur[base + i] = run;
        run += v;
    }
    if (t == 255) g_off[N_NODES] = run;
    __syncthreads();
}

__device__ void spmm_unit2(int u, const float* eb1, const float* eb2) {
    int node = u * 4 + (threadIdx.x >> 6);
    int c = threadIdx.x & 63;
    const uint2* w1 = (const uint2*)g_ew1h;
    const uint2* w2 = (const uint2*)g_ew2h;
    float4 a1 = ((const float4*)eb1)[c];
    float4 a2 = ((const float4*)eb2)[c];
    int s = g_off[node];
    int e = g_off[node + 1];
    for (int k = s; k < e; k++) {
        int j = g_csr[k] * 64 + c;
        uint2 v1 = w1[j];
        uint2 v2 = w2[j];
        float2 p0 = __half22float2(*(const __half2*)&v1.x);
        float2 p1 = __half22float2(*(const __half2*)&v1.y);
        a1.x += p0.x; a1.y += p0.y; a1.z += p1.x; a1.w += p1.y;
        float2 q0 = __half22float2(*(const __half2*)&v2.x);
        float2 q1 = __half22float2(*(const __half2*)&v2.y);
        a2.x += q0.x; a2.y += q0.y; a2.z += q1.x; a2.w += q1.y;
    }
    ((uint2*)g_e)[node * 64 + c]  = pack4h(a1);
    ((uint2*)g_e2)[node * 64 + c] = pack4h(a2);
}

// ================= HMMA fp16 GEMM phase =====================================
#define STAGES   3
#define BUF_SZ   32768
#define STATS_OFF (STAGES * BUF_SZ)
#define SMEM_MMA (STATS_OFF + 1024)

// KHALF: skip the B-compensation (lo) half -> NC=4 (mode 2/3 only).
// WGEN != 0 (MODE 1): wait for 17 builder flags before chunk-8 loads.
template <int MODE, bool F32S, bool HST, bool XCOPY, bool KHALF>
__device__ __noinline__ void gemm_phase(char* smem, int cta,
        const __half* A, const __half* A2,
        const __half* Bb, const __half* B2b,
        const float* bias,
        float* outf, int ldout, __half* oh,
        float* sumP, float* sqP, const float* xsrc,
        unsigned wgen) {
    const unsigned sbase = smem_u32(smem);
    const int tid = threadIdx.x;
    const int lane = tid & 31;
    const int w = tid >> 5;
    const int wm = w & 3;
    const int wn = w >> 2;
    const int bm = (cta >> 1) * 128;
    const int bn = (cta & 1) * 128;

    const int NC = (MODE == 1) ? 16 : (KHALF ? 4 : 8);

    auto issue = [&](int c) {
        const bool second = (MODE == 1) && (c >= 8);
        const int local = second ? c - 8 : c;
        const __half* Ap = second ? A2 : A;
        const __half* Bp = second ? B2b : Bb;
        const int ka = (local & 3) << 6;
        const int kb = local << 6;
        const unsigned sa = sbase + (c % STAGES) * BUF_SZ;
        const unsigned sb = sa + 16384;
#pragma unroll
        for (int i = 0; i < 4; i++) {
            int u = tid + (i << 8);
            int row = u >> 3, seg = u & 7;
            cp16(sa + row * 128 + ((seg ^ (row & 7)) << 4),
                 Ap + ((bm + row) << 8) + ka + (seg << 3));
        }
#pragma unroll
        for (int i = 0; i < 4; i++) {
            int u = tid + (i << 8);
            int row = u >> 3, seg = u & 7;
            cp16(sb + row * 128 + ((seg ^ (row & 7)) << 4),
                 Bp + (bn + row) * 512 + kb + (seg << 3));
        }
        cp_commit();
    };

    const int a_row = wm * 32 + (lane & 15);
    const int a_kh = lane >> 4;
    const int b_nrel = ((lane >> 4) << 3) + (lane & 7);
    const int b_n = wn * 64 + b_nrel;
    const int b_kh = (lane >> 3) & 1;

    float acc[2][8][4];
#pragma unroll
    for (int mt = 0; mt < 2; mt++)
#pragma unroll
        for (int nt = 0; nt < 8; nt++)
#pragma unroll
            for (int q = 0; q < 4; q++) acc[mt][nt][q] = 0.f;

    issue(0); issue(1); issue(2);

    for (int c = 0; c < NC; c++) {
        if (c >= NC - 2) cp_wait<0>(); else cp_wait<STAGES - 1>();
        __syncthreads();
        const unsigned sa = sbase + (c % STAGES) * BUF_SZ;
        const unsigned sb = sa + 16384;
#pragma unroll
        for (int ks = 0; ks < 4; ks++) {
            const int seg0 = ks * 2;
            unsigned af[2][4];
#pragma unroll
            for (int mt = 0; mt < 2; mt++) {
                int r = a_row + mt * 16;
                ldsm_x4(af[mt], sa + r * 128 + (((seg0 + a_kh) ^ (r & 7)) << 4));
            }
            unsigned bf[8][2];
#pragma unroll
            for (int np = 0; np < 4; np++) {
                int n = b_n + np * 16;
                unsigned t4[4];
                ldsm_x4(t4, sb + n * 128 + (((seg0 + b_kh) ^ (n & 7)) << 4));
                bf[np * 2][0] = t4[0]; bf[np * 2][1] = t4[1];
                bf[np * 2 + 1][0] = t4[2]; bf[np * 2 + 1][1] = t4[3];
            }
#pragma unroll
            for (int mt = 0; mt < 2; mt++)
#pragma unroll
                for (int nt = 0; nt < 8; nt++)
                    mma_fp16(acc[mt][nt], af[mt], bf[nt]);
        }
        __syncthreads();
        if (MODE == 1 && wgen && c + STAGES == 8) wait17(wgen);
        if (c + STAGES < NC) issue(c + STAGES);
    }
    __syncthreads();

    const int er = lane >> 2;
    const int ec = (lane & 3) << 1;
#pragma unroll
    for (int mt = 0; mt < 2; mt++) {
#pragma unroll
        for (int nt = 0; nt < 8; nt++) {
            int r0 = wm * 32 + mt * 16 + er;
            int cc = wn * 64 + nt * 8 + ec;
            float b0 = __ldcg(bias + bn + cc), b1 = __ldcg(bias + bn + cc + 1);
            float v0 = acc[mt][nt][0] + b0, v1 = acc[mt][nt][1] + b1;
            float v2 = acc[mt][nt][2] + b0, v3 = acc[mt][nt][3] + b1;
            if (MODE == 1 || MODE == 2) {
                v0 = fmaxf(v0, 0.f); v1 = fmaxf(v1, 0.f);
                v2 = fmaxf(v2, 0.f); v3 = fmaxf(v3, 0.f);
            }
            int r1 = r0 + 8;
            *(float2*)(smem + r0 * 512 + ((((cc >> 2) ^ ((r0 & 7) << 2))) << 4) + ((cc & 3) << 2)) = make_float2(v0, v1);
            *(float2*)(smem + r1 * 512 + ((((cc >> 2) ^ ((r1 & 7) << 2))) << 4) + ((cc & 3) << 2)) = make_float2(v2, v3);
        }
    }
    __syncthreads();

#pragma unroll 4
    for (int i = 0; i < 16; i++) {
        int u = tid + (i << 8);
        int r = u >> 5, seg = u & 31;
        float4 v = *(const float4*)(smem + r * 512 + ((seg ^ ((r & 7) << 2)) << 4));
        int grow = bm + r;
        int gcol = bn + (seg << 2);
        if (F32S) {
            *(float4*)(outf + grow * ldout + gcol) = v;
            if (XCOPY) {
                float4 xv = ((const float4*)xsrc)[(grow << 6) + (gcol >> 2)];
                *(float4*)(outf + grow * ldout + 256 + gcol) = xv;
            }
        }
        if (HST)  ((uint2*)oh)[(grow << 6) + (gcol >> 2)] = pack4h(v);
    }

    if (MODE == 2) {
        int c = tid & 127, r0 = (tid >> 7) << 6;
        float s = 0.f, q = 0.f;
#pragma unroll 4
        for (int rr = 0; rr < 64; rr++) {
            int r = r0 + rr;
            float v = *(const float*)(smem + r * 512 +
                                      ((((c >> 2) ^ ((r & 7) << 2))) << 4) + ((c & 3) << 2));
            s += v;
            q += v * v;
        }
        float* st = (float*)(smem + STATS_OFF);
        __syncthreads();
        if (tid >= 128) { st[c] = s; st[128 + c] = q; }
        __syncthreads();
        if (tid < 128) {
            atomicAdd(&sumP[bn + c], s + st[c]);
            atomicAdd(&sqP [bn + c], q + st[128 + c]);
        }
    }
    __syncthreads();
}

// ================= the mega kernel ==========================================
struct Params {
    const float* x;
    const int* ei;
    const float* P1[14];
    const float* P2[14];
    float* out;
};

__global__ __launch_bounds__(256, 2) void mega_k(Params P) {
    extern __shared__ char smem[];
    const int cta = blockIdx.x;
    unsigned gen = __ldcg(&g_flags[cta]);

    // ---- P0: hist (all CTAs, tiny) + wx tiles + biasr1 ----
    // (g_deg zero via static init on first launch, scatter phase afterwards)
    for (int u = cta; u < 1024; u += 256) {
        int e = u * 256 + threadIdx.x;
        atomicAdd(&g_deg[P.ei[N_EDGES + e]], 1);
    }
    if (cta < 16) {
        wx_tile<true>(smem, P.P2[2], P.P2[6], g_wx2, (cta >> 2) * 64, (cta & 3) * 64);
    } else if (cta < 32) {
        wx_tile<true>(smem, P.P1[2], P.P1[6], g_wx1, ((cta - 16) >> 2) * 64, ((cta - 16) & 3) * 64);
    } else if (cta == 32) {
        int n = threadIdx.x;
        float s = P.P1[5][n] + P.P1[7][n] + P.P1[3][n];
        for (int k = 0; k < 256; k++) s += P.P1[3][k] * P.P1[6][k * 256 + n];
        g_biasr[n] = s;
    }
    grid_bar(++gen);

    // ---- P1: CTA0 scans (publishes flag early); others: G tiles + splits +
    //          all conversions; then everyone waits scan flag and scatters ----
    ++gen;
    if (cta == 0) {
        scan256(smem);
        __threadfence();
        if (threadIdx.x == 0) atomicExch(&g_scan, gen);
    } else {
        if (cta < 17) {
            wx_tile<false>(smem, P.P1[12], g_wx2, g_G, ((cta - 1) >> 2) * 64, ((cta - 1) & 3) * 64);
        } else if (cta < 97) {
            int b = cta - 17;
            int mat = b >> 4, t = b & 15;
            const float* W;
            __half* B;
            bool addI = false;
            switch (mat) {
                case 0: W = P.P1[4]; B = g_Bw1a; addI = true; break;
                case 1: W = P.P1[8]; B = g_Bf1a; break;
                case 2: W = P.P2[4]; B = g_Bw1b; addI = true; break;
                case 3: W = P.P2[8]; B = g_Bf1b; break;
                default: W = g_wx1;  B = g_Bwx; break;
            }
            split_tile(smem, W, B, addI, t);
        }
        // conversions distributed over CTAs 1..255 (CTA0 is busy scanning)
        for (unsigned u = cta - 1; u < 12289u; u += 255)
            conv_unit(u, P.x, P.P1[0], P.P2[0]);
    }
    // wait for scan, then scatter + zero deg
    for (;;) {
        unsigned v = __ldcg(&g_scan);
        if (__syncthreads_and((int)(v - gen) >= 0)) break;
        __nanosleep(128);
    }
    __threadfence();
    for (int u = cta; u < 1024; u += 256) {
        int e = u * 256 + threadIdx.x;
        int d = P.ei[N_EDGES + e];
        int p = atomicAdd(&g_cur[d], 1);
        g_csr[p] = P.ei[e];
    }
    if (cta < 64) g_deg[cta * 256 + threadIdx.x] = 0;
    grid_bar(++gen);

    // ---- P2: merged spmm, pair-local rows ----
    {
        int u0 = (cta >> 1) * 32 + (cta & 1) * 16;
        for (int u = u0; u < u0 + 16; u++)
            spmm_unit2(u, P.P1[1], P.P2[1]);
    }
    pair_bar(++gen);

    // ---- P3: r1 = relu(emb1@(I+c1w1) + x@wx1 + biasr1) ----
    gemm_phase<1, false, true, false, false>(smem, cta, g_e, g_x, g_Bw1a, g_Bwx,
                                             g_biasr, nullptr, 0, g_r,
                                             nullptr, nullptr, nullptr, 0);
    pair_bar(++gen);

    // ---- P4: q1 = relu(r1@f1w1_hi + f1b1), stats1 (KHALF); publish ----
    gemm_phase<2, false, true, false, true>(smem, cta, g_r, nullptr, g_Bf1a, nullptr,
                                            P.P1[9], nullptr, 0, g_q,
                                            g_sum1, g_sq1, nullptr, 0);
    ++gen;
    publish(gen);

    // Builders (CTAs 0-16): wait all stats1, build B2 + layer2 bias, flag.
    if (cta < 17) {
        wait_all(gen);
        if (cta < 16) {
            split_tile_sc(smem, g_G, g_B2, g_sum1, g_sq1, P.P1[10], cta);
        } else {
            const float inv_n = 1.f / (float)N_NODES;
            int n = threadIdx.x;
            float s = P.P2[5][n] + P.P2[7][n] + P.P2[3][n];
            for (int k = 0; k < 256; k++) {
                float mu = __ldcg(g_sum1 + k) * inv_n;
                float var = __ldcg(g_sq1 + k) * inv_n - mu * mu;
                float rs = rsqrtf(var + BN_EPS);
                float t1 = P.P1[11][k] - mu * rs * P.P1[10][k];
                s += P.P2[3][k] * P.P2[6][k * 256 + n] + t1 * g_G[(k << 8) + n]
                   + P.P1[13][k] * g_wx2[(k << 8) + n];
            }
            g_biasr[n] = s;
        }
        __syncthreads();
        __threadfence();
        if (threadIdx.x == 0) atomicExch(&g_bflag[cta], gen);
    }

    // ---- P5: r2 = relu(emb2@(I+c1w2) + q1@B2 + biasr2); builder wait inline --
    gemm_phase<1, false, true, false, false>(smem, cta, g_e2, g_q, g_Bw1b, g_B2,
                                             g_biasr, nullptr, 0, g_r,
                                             nullptr, nullptr, nullptr, gen);
    pair_bar(++gen);

    // ---- P6: q2 = relu(r2@f1w2_hi + f1b2), stats2 (KHALF); publish ----
    gemm_phase<2, false, true, false, true>(smem, cta, g_r, nullptr, g_Bf1b, nullptr,
                                            P.P2[9], nullptr, 0, g_q,
                                            g_sum2, g_sq2, nullptr, 0);
    ++gen;
    publish(gen);

    // Builders: wait all stats2, build Bf2 + bias3, flag.
    if (cta < 17) {
        wait_all(gen);
        if (cta < 16) {
            split_tile_sc(smem, P.P2[12], g_Bf2, g_sum2, g_sq2, P.P2[10], cta);
        } else {
            const float inv_n = 1.f / (float)N_NODES;
            int n = threadIdx.x;
            float s = P.P2[13][n];
            for (int k = 0; k < 256; k++) {
                float mu = __ldcg(g_sum2 + k) * inv_n;
                float var = __ldcg(g_sq2 + k) * inv_n - mu * mu;
                float rs = rsqrtf(var + BN_EPS);
                s += (P.P2[11][k] - mu * rs * P.P2[10][k]) * P.P2[12][(k << 8) + n];
            }
            g_bias3[n] = s;
        }
        __syncthreads();
        __threadfence();
        if (threadIdx.x == 0) atomicExch(&g_bflag[cta], gen);
    }
    wait17(gen);

    // ---- P7: out[:,0:256] = (q2*s2+t2)@f2w2 + f2b2 ; out[:,256:512] = x ----
    gemm_phase<3, true, false, true, false>(smem, cta, g_q, nullptr, g_Bf2, nullptr,
                                            g_bias3, P.out, 512, nullptr,
                                            nullptr, nullptr, P.x, 0);
}

// ================= host orchestration ========================================
extern "C" void kernel_launch(void* const* d_in, const int* in_sizes, int n_in,
                              void* d_out, int out_size) {
    (void)in_sizes; (void)n_in; (void)out_size;

    Params P;
    P.x  = (const float*)d_in[0];
    P.ei = (const int*)d_in[2];
    for (int i = 0; i < 14; i++) {
        P.P1[i] = (const float*)d_in[4 + i];
        P.P2[i] = (const float*)d_in[18 + i];
    }
    P.out = (float*)d_out;

    cudaFuncSetAttribute(mega_k, cudaFuncAttributeMaxDynamicSharedMemorySize,
                         SMEM_MMA);

    mega_k<<<256, 256, SMEM_MMA>>>(P);
}